// round 3
// baseline (speedup 1.0000x reference)
#include <cuda_runtime.h>
#include <stdint.h>

// ---------------------------------------------------------------------------
// Raindrop ObservationPropagation, use_beta=False, heads=1.
// Identity: message uses x[tgt] (constant within each softmax segment) and the
// segment softmax gamma sums to exactly 1, so
//   out[n] = relu(x[n] @ Wv + bv) * has_incoming_edge[n]
// edge_weights cancel. Work = edge-target mask scatter + masked 50000x96x96
// GEMM (bias+relu epilogue), done with packed fp32x2 FFMA.
// ---------------------------------------------------------------------------

#define DIM 96
#define RPB 64            // rows per block
#define SXT_S 68          // padded inner dim of k-major x tile (bank-conflict-free)
#define MAX_NODES (1 << 18)

__device__ unsigned char g_mask[MAX_NODES];
__device__ int g_is64 = 1;   // monotonic: only ever cleared (idempotent across replays)

// Zero the node mask (word stores) + detect edge_index width.
// Detection: sample first nsample 64-bit words (source row, in-bounds under
// both interpretations). int64 -> values in [0,n); int32 -> packed pair,
// value >= 2^32 almost surely. Only writes 0 -> no reset race, deterministic.
__global__ void rd_init_kernel(const long long* __restrict__ ei,
                               int nwords, int nsample, int n_nodes) {
    int i = blockIdx.x * blockDim.x + threadIdx.x;
    if (i < nwords) ((int*)g_mask)[i] = 0;
    if (i < nsample) {
        long long v = ei[i];
        if (v < 0 || v >= (long long)n_nodes) g_is64 = 0;
    }
}

// mask[tgt[e]] = 1 (skip if already set: cuts ~800k stores to ~50k).
__global__ void rd_scatter_kernel(const void* __restrict__ ei,
                                  long long E, int n_nodes) {
    const int is64 = g_is64;
    long long e = (long long)blockIdx.x * blockDim.x + threadIdx.x;
    if (e >= E) return;
    long long t;
    if (is64) t = ((const long long*)ei)[E + e];
    else      t = (long long)((const int*)ei)[E + e];
    if (t >= 0 && t < (long long)n_nodes && !g_mask[t]) g_mask[t] = 1;
}

#define FMA2(d, a, b) asm("fma.rn.f32x2 %0, %1, %2, %3;" \
                          : "=l"(d) : "l"(a), "l"(b), "l"(d))

// out[n] = mask[n] * relu(x[n] @ Wv + bv)
// Block 256 = 8 warps; 64 rows/block. Warp w owns rows [8w, 8w+8) as 4
// row-pairs; lane tx owns cols {tx, tx+32, tx+64}. x tile k-major in
// sXT[k][row] (pad 68): the 8 row-activations per k are 2 broadcast LDS.128
// read directly as f32x2 pairs. Per k-step: 2 LDS.128 + 3 LDS.32 + 12 FFMA2.
__global__ __launch_bounds__(256, 3)
void rd_gemm_kernel(const float* __restrict__ x,
                    const float* __restrict__ Wv,
                    const float* __restrict__ bv,
                    float* __restrict__ out, int n) {
    __shared__ float sW[DIM * DIM];                       // 36864 B
    __shared__ float sB[DIM];
    __shared__ __align__(16) float sXT[DIM][SXT_S];       // 26112 B

    const int tid  = threadIdx.x;
    const int row0 = blockIdx.x * RPB;

    // Wv: 2304 float4, 9 per thread.
    {
        const float4* W4 = (const float4*)Wv;
        float4* sW4 = (float4*)sW;
#pragma unroll
        for (int i = 0; i < 9; i++) sW4[tid + 256 * i] = W4[tid + 256 * i];
    }
    if (tid < DIM) sB[tid] = bv[tid];

    // Transposed x tile load, conflict-free:
    // unit u = rg*96 + k (rg=row-group of 4, k=column). Thread gathers 4 rows
    // at column k (4 coalesced LDG.32 across the warp: consecutive k) and
    // stores ONE STS.128 at sXT[k][rg*4]. With stride 68, lane k-stride is
    // 68 words == 4 banks -> 8 lanes cover all 32 banks -> 0 conflicts.
    const bool full = (row0 + RPB <= n);
#pragma unroll
    for (int it = 0; it < 6; it++) {
        int u  = tid + 256 * it;        // 0..1535
        int rg = u / DIM;               // 0..15
        int k  = u - rg * DIM;          // 0..95
        int r  = row0 + rg * 4;
        float v0 = 0.f, v1 = 0.f, v2 = 0.f, v3 = 0.f;
        if (full) {
            v0 = x[(size_t)(r + 0) * DIM + k];
            v1 = x[(size_t)(r + 1) * DIM + k];
            v2 = x[(size_t)(r + 2) * DIM + k];
            v3 = x[(size_t)(r + 3) * DIM + k];
        } else {
            if (r + 0 < n) v0 = x[(size_t)(r + 0) * DIM + k];
            if (r + 1 < n) v1 = x[(size_t)(r + 1) * DIM + k];
            if (r + 2 < n) v2 = x[(size_t)(r + 2) * DIM + k];
            if (r + 3 < n) v3 = x[(size_t)(r + 3) * DIM + k];
        }
        *(float4*)&sXT[k][rg * 4] = make_float4(v0, v1, v2, v3);
    }
    __syncthreads();

    const int tx = tid & 31;
    const int wr = (tid >> 5) * 8;      // first of this warp's 8 rows

    unsigned long long acc[4][3];       // [row-pair][col-group], packed f32x2
#pragma unroll
    for (int p = 0; p < 4; p++)
#pragma unroll
        for (int c = 0; c < 3; c++) acc[p][c] = 0ull;

#pragma unroll 8
    for (int k = 0; k < DIM; k++) {
        // 8 rows as 4 f32x2 pairs: two broadcast LDS.128 (16B-aligned: wr%8==0)
        ulonglong2 xa = *(const ulonglong2*)&sXT[k][wr];       // pairs (0,1),(2,3)
        ulonglong2 xb = *(const ulonglong2*)&sXT[k][wr + 4];   // pairs (4,5),(6,7)
        unsigned int w0 = __float_as_uint(sW[k * DIM + tx]);
        unsigned int w1 = __float_as_uint(sW[k * DIM + tx + 32]);
        unsigned int w2 = __float_as_uint(sW[k * DIM + tx + 64]);
        unsigned long long wd0, wd1, wd2;
        asm("mov.b64 %0, {%1, %1};" : "=l"(wd0) : "r"(w0));
        asm("mov.b64 %0, {%1, %1};" : "=l"(wd1) : "r"(w1));
        asm("mov.b64 %0, {%1, %1};" : "=l"(wd2) : "r"(w2));
        FMA2(acc[0][0], xa.x, wd0); FMA2(acc[0][1], xa.x, wd1); FMA2(acc[0][2], xa.x, wd2);
        FMA2(acc[1][0], xa.y, wd0); FMA2(acc[1][1], xa.y, wd1); FMA2(acc[1][2], xa.y, wd2);
        FMA2(acc[2][0], xb.x, wd0); FMA2(acc[2][1], xb.x, wd1); FMA2(acc[2][2], xb.x, wd2);
        FMA2(acc[3][0], xb.y, wd0); FMA2(acc[3][1], xb.y, wd1); FMA2(acc[3][2], xb.y, wd2);
    }

    const float b0 = sB[tx];
    const float b1 = sB[tx + 32];
    const float b2 = sB[tx + 64];

#pragma unroll
    for (int p = 0; p < 4; p++) {
        int r = row0 + wr + 2 * p;      // low half of pair = even row
#pragma unroll
        for (int half = 0; half < 2; half++) {
            int rr = r + half;
            if (rr < n) {
                float m = g_mask[rr] ? 1.f : 0.f;
                float a0 = __uint_as_float((unsigned int)(acc[p][0] >> (half * 32)));
                float a1 = __uint_as_float((unsigned int)(acc[p][1] >> (half * 32)));
                float a2 = __uint_as_float((unsigned int)(acc[p][2] >> (half * 32)));
                float* o = out + (size_t)rr * DIM;
                o[tx]      = fmaxf(a0 + b0, 0.f) * m;
                o[tx + 32] = fmaxf(a1 + b1, 0.f) * m;
                o[tx + 64] = fmaxf(a2 + b2, 0.f) * m;
            }
        }
    }
}

extern "C" void kernel_launch(void* const* d_in, const int* in_sizes, int n_in,
                              void* d_out, int out_size) {
    const float* x  = (const float*)d_in[0];
    // d_in[1] = p_t (unused, use_beta=False)
    const float* Wv = (const float*)d_in[2];
    const float* bv = (const float*)d_in[3];
    // d_in[4] = edge_weights (cancels: segment softmax sums to 1)
    const void*  ei = d_in[5];

    const int n = in_sizes[0] / DIM;                 // 50000
    const long long E = (long long)in_sizes[5] / 2;  // 800000

    {   // 1) zero mask (word stores) + width detection, fused
        int nwords  = (n + 3) / 4;
        int nsample = (int)((E / 2 < 8192) ? E / 2 : 8192);
        int work = nwords > nsample ? nwords : nsample;
        int threads = 256;
        int blocks = (work + threads - 1) / threads;
        rd_init_kernel<<<blocks, threads>>>((const long long*)ei, nwords, nsample, n);
    }
    {   // 2) scatter edge-target mask (store-skip)
        int threads = 256;
        int blocks = (int)((E + threads - 1) / threads);
        rd_scatter_kernel<<<blocks, threads>>>(ei, E, n);
    }
    {   // 3) masked GEMM + bias + relu
        int blocks = (n + RPB - 1) / RPB;
        rd_gemm_kernel<<<blocks, 256>>>(x, Wv, bv, (float*)d_out, n);
    }
}